// round 9
// baseline (speedup 1.0000x reference)
#include <cuda_runtime.h>
#include <math.h>

// Problem constants (fixed by setup_inputs)
#define NBATCH 2
#define NPB_NODES 20000           // nodes per batch
#define BN (NBATCH * NPB_NODES)   // 40000 total nodes
#define KNB 32                    // max neighbors
#define H 128                     // hidden dim (= F)
#define C 40                      // classes
#define NPW 8
#define NGROUPS (BN / NPW)

#define THREADS_EMB 256
#define THREADS_GEMM 384
#define THREADS_GAT 512
#define THREADS_CLS 512
#define NWARPS_CLS  16
#define GRID 148
#define TOTAL_WARPS_CLS (GRID * NWARPS_CLS)

// Scratch buffers
__device__ float g_h0[BN * H];
__device__ float g_h1[BN * H];
__device__ float g_y [BN * H];
__device__ float g_u [BN * H];

// packed f32x2 helpers
#define FMA2(acc, a, b) asm("fma.rn.f32x2 %0, %1, %2, %0;" : "+l"(acc) : "l"(a), "l"(b))
#define PACK2(d, s)     asm("mov.b64 %0, {%1, %1};" : "=l"(d) : "f"(s))
#define UNPACK2(lo, hi, s) asm("mov.b64 {%0, %1}, %2;" : "=f"(lo), "=f"(hi) : "l"(s))

// ---------------------------------------------------------------------------
// Embed: h = (X @ W_embed) / rowsum(X). (unchanged, known-good)
// ---------------------------------------------------------------------------
extern "C" __global__ void __launch_bounds__(THREADS_EMB)
embed_kernel(const float* __restrict__ X, const float* __restrict__ W,
             float* __restrict__ out)
{
    extern __shared__ float sm[];
    float* Wsh = sm;                  // 16384 floats
    float* xs  = sm + 16384;          // 32*128

    const int tid  = threadIdx.x;
    const int lane = tid & 31;
    const int w    = tid >> 5;

    for (int i = tid; i < H * H; i += THREADS_EMB) Wsh[i] = W[i];
    __syncthreads();

    float* xsw = xs + (w * 4) * H;
    const float4* X4 = (const float4*)X;

    const int gw = blockIdx.x * (THREADS_EMB / 32) + w;
    const int nwarps_total = gridDim.x * (THREADS_EMB / 32);
    for (int g = gw; g < BN / 4; g += nwarps_total) {
        const int base = g * 4;
        float inv[4];
        #pragma unroll
        for (int j = 0; j < 4; j++) {
            float4 v = X4[(base + j) * 32 + lane];
            ((float4*)(xsw + j * H))[lane] = v;
            float s = v.x + v.y + v.z + v.w;
            #pragma unroll
            for (int o = 16; o; o >>= 1) s += __shfl_xor_sync(0xffffffffu, s, o);
            inv[j] = 1.0f / s;
        }
        __syncwarp();

        unsigned long long axy[4], azw[4];
        #pragma unroll
        for (int j = 0; j < 4; j++) { axy[j] = 0ull; azw[j] = 0ull; }

        #pragma unroll 2
        for (int f0 = 0; f0 < H; f0 += 4) {
            ulonglong2 wv[4];
            #pragma unroll
            for (int q = 0; q < 4; q++)
                wv[q] = ((const ulonglong2*)(Wsh + (f0 + q) * H))[lane];
            #pragma unroll
            for (int j = 0; j < 4; j++) {
                float4 av = *(const float4*)(xsw + j * H + f0);
                unsigned long long aa;
                PACK2(aa, av.x); FMA2(axy[j], aa, wv[0].x); FMA2(azw[j], aa, wv[0].y);
                PACK2(aa, av.y); FMA2(axy[j], aa, wv[1].x); FMA2(azw[j], aa, wv[1].y);
                PACK2(aa, av.z); FMA2(axy[j], aa, wv[2].x); FMA2(azw[j], aa, wv[2].y);
                PACK2(aa, av.w); FMA2(axy[j], aa, wv[3].x); FMA2(azw[j], aa, wv[3].y);
            }
        }
        #pragma unroll
        for (int j = 0; j < 4; j++) {
            float x, y, z, u;
            UNPACK2(x, y, axy[j]);
            UNPACK2(z, u, azw[j]);
            float4 o = make_float4(x * inv[j], y * inv[j], z * inv[j], u * inv[j]);
            ((float4*)out)[(base + j) * 32 + lane] = o;
        }
        __syncwarp();
    }
}

// ---------------------------------------------------------------------------
// Dense GEMM: Y = h@W, U = h@B  (concatenated 256 output dims)
// CTA: 384 thr = 12 warps: warp = (wn 0..2 nodes, wd 0..3 dims*64)
// warp tile 32 nodes x 64 dims; thread 8 nodes x 8 dims (8x8 reg blocking)
// smem: Ws[128][256] (128KB) + As[96][128] (48KB)
// ---------------------------------------------------------------------------
extern "C" __global__ void __launch_bounds__(THREADS_GEMM, 1)
gemm2_kernel(const float* __restrict__ hin,
             const float* __restrict__ Wp, const float* __restrict__ Bp,
             float* __restrict__ Yp, float* __restrict__ Up)
{
    extern __shared__ float sm[];
    float* Ws = sm;                 // 128*256
    float* As = sm + 128 * 256;     // 96*128

    const int tid  = threadIdx.x;
    const int lane = tid & 31;
    const int w    = tid >> 5;
    const int wd   = w & 3;         // dim block *64
    const int wn   = w >> 2;        // node block *32
    const int r    = lane >> 3;     // node subgroup *8
    const int c    = lane & 7;      // dim subgroup *8

    // concatenated weights: [f][0..127]=W, [f][128..255]=B
    for (int i = tid; i < H * H; i += THREADS_GEMM) {
        int f = i >> 7, d = i & 127;
        Ws[f * 256 + d]       = Wp[i];
        Ws[f * 256 + 128 + d] = Bp[i];
    }
    __syncthreads();

    const float4* h4 = (const float4*)hin;
    float4* Y4 = (float4*)Yp;
    float4* U4 = (float4*)Up;

    const int d0   = wd * 64 + c * 8;       // 0..248
    const bool isY = (d0 < 128);
    const int dloc = isY ? d0 : d0 - 128;
    const float* Asw = As + (wn * 32 + r * 8) * H;

    for (int tb = blockIdx.x * 96; tb < BN; tb += gridDim.x * 96) {
        // stage act tile (coalesced, zero-pad OOB)
        for (int i = tid; i < 96 * 32; i += THREADS_GEMM) {
            int nl = i >> 5, f4 = i & 31;
            int node = tb + nl;
            float4 v = (node < BN) ? h4[node * 32 + f4] : make_float4(0.f, 0.f, 0.f, 0.f);
            ((float4*)As)[nl * 32 + f4] = v;
        }
        __syncthreads();

        unsigned long long acc[8][4];
        #pragma unroll
        for (int j = 0; j < 8; j++)
            #pragma unroll
            for (int q = 0; q < 4; q++) acc[j][q] = 0ull;

        #pragma unroll 2
        for (int f0 = 0; f0 < H; f0 += 4) {
            ulonglong2 wlo[4], whi[4];
            #pragma unroll
            for (int q = 0; q < 4; q++) {
                wlo[q] = *(const ulonglong2*)(Ws + (f0 + q) * 256 + d0);
                whi[q] = *(const ulonglong2*)(Ws + (f0 + q) * 256 + d0 + 4);
            }
            #pragma unroll
            for (int j = 0; j < 8; j++) {
                float4 av = *(const float4*)(Asw + j * H + f0);
                unsigned long long aa;
                PACK2(aa, av.x);
                FMA2(acc[j][0], aa, wlo[0].x); FMA2(acc[j][1], aa, wlo[0].y);
                FMA2(acc[j][2], aa, whi[0].x); FMA2(acc[j][3], aa, whi[0].y);
                PACK2(aa, av.y);
                FMA2(acc[j][0], aa, wlo[1].x); FMA2(acc[j][1], aa, wlo[1].y);
                FMA2(acc[j][2], aa, whi[1].x); FMA2(acc[j][3], aa, whi[1].y);
                PACK2(aa, av.z);
                FMA2(acc[j][0], aa, wlo[2].x); FMA2(acc[j][1], aa, wlo[2].y);
                FMA2(acc[j][2], aa, whi[2].x); FMA2(acc[j][3], aa, whi[2].y);
                PACK2(aa, av.w);
                FMA2(acc[j][0], aa, wlo[3].x); FMA2(acc[j][1], aa, wlo[3].y);
                FMA2(acc[j][2], aa, whi[3].x); FMA2(acc[j][3], aa, whi[3].y);
            }
        }

        #pragma unroll
        for (int j = 0; j < 8; j++) {
            int node = tb + wn * 32 + r * 8 + j;
            if (node < BN) {
                float x0, x1, x2, x3, x4, x5, x6, x7;
                UNPACK2(x0, x1, acc[j][0]);
                UNPACK2(x2, x3, acc[j][1]);
                UNPACK2(x4, x5, acc[j][2]);
                UNPACK2(x6, x7, acc[j][3]);
                float4 lo = make_float4(x0, x1, x2, x3);
                float4 hi = make_float4(x4, x5, x6, x7);
                if (isY) {
                    Y4[node * 32 + (dloc >> 2)]     = lo;
                    Y4[node * 32 + (dloc >> 2) + 1] = hi;
                } else {
                    U4[node * 32 + (dloc >> 2)]     = lo;
                    U4[node * 32 + (dloc >> 2) + 1] = hi;
                }
            }
        }
        __syncthreads();   // before next tile overwrites As
    }
}

// ---------------------------------------------------------------------------
// Gather + residual + relu: h' = relu( (sum_K Y[nbr]) / max(vlen,1) + U )
// No weights, tiny footprint -> high occupancy streaming kernel.
// ---------------------------------------------------------------------------
extern "C" __global__ void __launch_bounds__(THREADS_GAT)
gather_relu_kernel(const float* __restrict__ Yp, const float* __restrict__ Up,
                   const int* __restrict__ nbr, const int* __restrict__ vlen,
                   float* __restrict__ hout)
{
    const int lane = threadIdx.x & 31;
    const int gw   = (blockIdx.x * THREADS_GAT + threadIdx.x) >> 5;
    const int nw   = (gridDim.x * THREADS_GAT) >> 5;
    const float4* Y4 = (const float4*)Yp;
    const float4* U4 = (const float4*)Up;

    for (int node = gw; node < BN; node += nw) {
        const int boff = (node >= NPB_NODES) ? NPB_NODES : 0;
        int myi = nbr[node * KNB + lane];

        float4 a0 = make_float4(0.f, 0.f, 0.f, 0.f);
        float4 a1 = make_float4(0.f, 0.f, 0.f, 0.f);
        float4 a2 = make_float4(0.f, 0.f, 0.f, 0.f);
        float4 a3 = make_float4(0.f, 0.f, 0.f, 0.f);
        #pragma unroll
        for (int k = 0; k < 8; k++) {
            int i0 = __shfl_sync(0xffffffffu, myi, k);
            int i1 = __shfl_sync(0xffffffffu, myi, k + 8);
            int i2 = __shfl_sync(0xffffffffu, myi, k + 16);
            int i3 = __shfl_sync(0xffffffffu, myi, k + 24);
            float4 v0 = Y4[(boff + i0) * 32 + lane];
            float4 v1 = Y4[(boff + i1) * 32 + lane];
            float4 v2 = Y4[(boff + i2) * 32 + lane];
            float4 v3 = Y4[(boff + i3) * 32 + lane];
            a0.x += v0.x; a0.y += v0.y; a0.z += v0.z; a0.w += v0.w;
            a1.x += v1.x; a1.y += v1.y; a1.z += v1.z; a1.w += v1.w;
            a2.x += v2.x; a2.y += v2.y; a2.z += v2.z; a2.w += v2.w;
            a3.x += v3.x; a3.y += v3.y; a3.z += v3.z; a3.w += v3.w;
        }
        int len = vlen[node];
        float inv = 1.0f / (float)(len > 0 ? len : 1);
        float4 u = U4[node * 32 + lane];
        float4 o;
        o.x = fmaxf((a0.x + a1.x + a2.x + a3.x) * inv + u.x, 0.f);
        o.y = fmaxf((a0.y + a1.y + a2.y + a3.y) * inv + u.y, 0.f);
        o.z = fmaxf((a0.z + a1.z + a2.z + a3.z) * inv + u.z, 0.f);
        o.w = fmaxf((a0.w + a1.w + a2.w + a3.w) * inv + u.w, 0.f);
        ((float4*)hout)[node * 32 + lane] = o;
    }
}

// ---------------------------------------------------------------------------
// Classifier (unchanged, known-good): z = relu(h@W1+b1); softmax(z@W2+b2)
// ---------------------------------------------------------------------------
extern "C" __global__ void __launch_bounds__(THREADS_CLS)
classifier_kernel(const float* __restrict__ hin,
                  const float* __restrict__ W1, const float* __restrict__ b1,
                  const float* __restrict__ W2, const float* __restrict__ b2,
                  float* __restrict__ out)
{
    extern __shared__ float sm[];
    float* W1sh = sm;
    float* W2sh = W1sh + 16384;
    float* b1sh = W2sh + H * C;
    float* b2sh = b1sh + H;
    float* zsh  = b2sh + C;

    const int tid  = threadIdx.x;
    const int lane = tid & 31;
    const int w    = tid >> 5;

    for (int i = tid; i < H * H; i += THREADS_CLS) W1sh[i] = W1[i];
    for (int i = tid; i < H * C; i += THREADS_CLS) W2sh[i] = W2[i];
    if (tid < H) b1sh[tid] = b1[tid];
    if (tid < C) b2sh[tid] = b2[tid];
    __syncthreads();

    float* zshw = zsh + (w * NPW) * H;
    const float4* h4 = (const float4*)hin;

    const int c2 = 32 + (lane & 7);
    const bool has2 = (lane < 8);

    const int gw = blockIdx.x * NWARPS_CLS + w;
    for (int g = gw; g < NGROUPS; g += TOTAL_WARPS_CLS) {
        const int base = g * NPW;

        #pragma unroll
        for (int n = 0; n < NPW; n++)
            ((float4*)(zshw + n * H))[lane] = h4[(base + n) * 32 + lane];
        __syncwarp();

        unsigned long long axy[NPW], azw[NPW];
        #pragma unroll
        for (int n = 0; n < NPW; n++) { axy[n] = 0ull; azw[n] = 0ull; }

        #pragma unroll 2
        for (int f0 = 0; f0 < H; f0 += 4) {
            ulonglong2 wv[4];
            #pragma unroll
            for (int q = 0; q < 4; q++)
                wv[q] = ((const ulonglong2*)(W1sh + (f0 + q) * H))[lane];
            #pragma unroll
            for (int n = 0; n < NPW; n++) {
                float4 av = *(const float4*)(zshw + n * H + f0);
                unsigned long long aa;
                PACK2(aa, av.x); FMA2(axy[n], aa, wv[0].x); FMA2(azw[n], aa, wv[0].y);
                PACK2(aa, av.y); FMA2(axy[n], aa, wv[1].x); FMA2(azw[n], aa, wv[1].y);
                PACK2(aa, av.z); FMA2(axy[n], aa, wv[2].x); FMA2(azw[n], aa, wv[2].y);
                PACK2(aa, av.w); FMA2(axy[n], aa, wv[3].x); FMA2(azw[n], aa, wv[3].y);
            }
        }

        float4 bb = ((const float4*)b1sh)[lane];
        float4 zreg[NPW];
        #pragma unroll
        for (int n = 0; n < NPW; n++) {
            float x, y, z, u;
            UNPACK2(x, y, axy[n]);
            UNPACK2(z, u, azw[n]);
            zreg[n] = make_float4(fmaxf(x + bb.x, 0.f), fmaxf(y + bb.y, 0.f),
                                  fmaxf(z + bb.z, 0.f), fmaxf(u + bb.w, 0.f));
        }
        __syncwarp();
        #pragma unroll
        for (int n = 0; n < NPW; n++)
            ((float4*)(zshw + n * H))[lane] = zreg[n];
        __syncwarp();

        float l1[NPW], l2[NPW];
        #pragma unroll
        for (int n = 0; n < NPW; n++) { l1[n] = b2sh[lane]; l2[n] = b2sh[c2]; }

        #pragma unroll 2
        for (int f0 = 0; f0 < H; f0 += 4) {
            float w2a[4], w2b[4];
            #pragma unroll
            for (int q = 0; q < 4; q++) {
                w2a[q] = W2sh[(f0 + q) * C + lane];
                w2b[q] = W2sh[(f0 + q) * C + c2];
            }
            #pragma unroll
            for (int n = 0; n < NPW; n++) {
                float4 zv = *(const float4*)(zshw + n * H + f0);
                l1[n] += zv.x * w2a[0] + zv.y * w2a[1];
                l1[n] += zv.z * w2a[2] + zv.w * w2a[3];
                l2[n] += zv.x * w2b[0] + zv.y * w2b[1];
                l2[n] += zv.z * w2b[2] + zv.w * w2b[3];
            }
        }

        #pragma unroll
        for (int n = 0; n < NPW; n++) {
            float m = fmaxf(l1[n], has2 ? l2[n] : -INFINITY);
            #pragma unroll
            for (int o = 16; o; o >>= 1) m = fmaxf(m, __shfl_xor_sync(0xffffffffu, m, o));
            float e1 = __expf(l1[n] - m);
            float e2 = has2 ? __expf(l2[n] - m) : 0.f;
            float s = e1 + e2;
            #pragma unroll
            for (int o = 16; o; o >>= 1) s += __shfl_xor_sync(0xffffffffu, s, o);
            float invs = 1.0f / s;
            out[(base + n) * C + lane] = e1 * invs;
            if (has2) out[(base + n) * C + c2] = e2 * invs;
        }
        __syncwarp();
    }
}

// ---------------------------------------------------------------------------
// Launch
// ---------------------------------------------------------------------------
#define EMBED_SMEM  ((16384 + 32 * H) * 4)
#define GEMM_SMEM   ((128 * 256 + 96 * 128) * 4)          // 180224 B
#define CLS_SMEM    ((16384 + H * C + H + C + NWARPS_CLS * NPW * H) * 4)

extern "C" void kernel_launch(void* const* d_in, const int* in_sizes, int n_in,
                              void* d_out, int out_size)
{
    const float* X    = (const float*)d_in[0];
    const int*   nbr  = (const int*)d_in[1];
    const int*   vlen = (const int*)d_in[2];
    const float* We   = (const float*)d_in[3];
    const float* gW   = (const float*)d_in[4];
    const float* gB   = (const float*)d_in[5];
    const float* W1   = (const float*)d_in[6];
    const float* b1   = (const float*)d_in[7];
    const float* W2   = (const float*)d_in[8];
    const float* b2   = (const float*)d_in[9];
    float* out = (float*)d_out;

    (void)in_sizes; (void)n_in; (void)out_size;

    cudaFuncSetAttribute(embed_kernel,      cudaFuncAttributeMaxDynamicSharedMemorySize, EMBED_SMEM);
    cudaFuncSetAttribute(gemm2_kernel,      cudaFuncAttributeMaxDynamicSharedMemorySize, GEMM_SMEM);
    cudaFuncSetAttribute(classifier_kernel, cudaFuncAttributeMaxDynamicSharedMemorySize, CLS_SMEM);

    float *h0, *h1, *yb, *ub;
    cudaGetSymbolAddress((void**)&h0, g_h0);
    cudaGetSymbolAddress((void**)&h1, g_h1);
    cudaGetSymbolAddress((void**)&yb, g_y);
    cudaGetSymbolAddress((void**)&ub, g_u);

    embed_kernel<<<296, THREADS_EMB, EMBED_SMEM>>>(X, We, h0);

    gemm2_kernel<<<GRID, THREADS_GEMM, GEMM_SMEM>>>(h0, gW + 0 * H * H, gB + 0 * H * H, yb, ub);
    gather_relu_kernel<<<296, THREADS_GAT>>>(yb, ub, nbr, vlen, h1);

    gemm2_kernel<<<GRID, THREADS_GEMM, GEMM_SMEM>>>(h1, gW + 1 * H * H, gB + 1 * H * H, yb, ub);
    gather_relu_kernel<<<296, THREADS_GAT>>>(yb, ub, nbr, vlen, h0);

    gemm2_kernel<<<GRID, THREADS_GEMM, GEMM_SMEM>>>(h0, gW + 2 * H * H, gB + 2 * H * H, yb, ub);
    gather_relu_kernel<<<296, THREADS_GAT>>>(yb, ub, nbr, vlen, h1);

    classifier_kernel<<<GRID, THREADS_CLS, CLS_SMEM>>>(h1, W1, b1, W2, b2, out);
}